// round 1
// baseline (speedup 1.0000x reference)
#include <cuda_runtime.h>
#include <cstdint>

// Problem constants (from reference setup_inputs)
#define KC   40      // number of codes
#define DC   492     // feature dim
#define D4C  123     // DC / 4
#define TPB  512     // threads per block (main kernel)
#define PPB  512     // points per block (1 point / thread)

#define DECAY 0.9f
#define EPSV  1e-5f

// ---------------- scratch (device globals; no allocations allowed) ----------
__device__ float g_dw[KC * DC];
__device__ float g_counts[KC];
__device__ float g_sumsq;

// ---------------- packed f32x2 FMA (Blackwell FFMA2; PTX-only path) ---------
__device__ __forceinline__ unsigned long long fma2(unsigned long long a,
                                                   unsigned long long b,
                                                   unsigned long long c) {
    unsigned long long d;
    asm("fma.rn.f32x2 %0, %1, %2, %3;" : "=l"(d) : "l"(a), "l"(b), "l"(c));
    return d;
}
__device__ __forceinline__ float f2_lo(unsigned long long v) {
    return __uint_as_float((unsigned)(v & 0xffffffffull));
}
__device__ __forceinline__ float f2_hi(unsigned long long v) {
    return __uint_as_float((unsigned)(v >> 32));
}

// ---------------- kernel 0: zero scratch ------------------------------------
__global__ void vq_zero_kernel() {
    int i = blockIdx.x * blockDim.x + threadIdx.x;
    if (i < KC * DC) g_dw[i] = 0.0f;
    if (i < KC)      g_counts[i] = 0.0f;
    if (i == 0)      g_sumsq = 0.0f;
}

// ---------------- kernel 1: assignment + per-block segment sums -------------
// SMEM layout (dynamic):
//   float buf[KC*DC]   : codebook during phase 1, reused as dw tile in phase 2
//   float e2[KC]       : squared norms of codes
//   int   sidx[PPB]    : per-point argmin index
//   int   scount[KC]   : per-block counts
//   float red[TPB/32]  : sumsq warp partials
__global__ void __launch_bounds__(TPB, 1)
vq_main_kernel(const float* __restrict__ X, int n_points) {
    extern __shared__ unsigned char smem_raw[];
    float* buf    = (float*)smem_raw;                 // KC*DC floats
    float* e2     = buf + KC * DC;                    // KC
    int*   sidx   = (int*)(e2 + KC);                  // PPB
    int*   scount = sidx + PPB;                       // KC
    float* red    = (float*)(scount + KC);            // TPB/32

    const int tid = threadIdx.x;
    const int bid = blockIdx.x;

    if (tid < KC) scount[tid] = 0;

    // Load codebook into SMEM (it sits at d_in[1]; passed via constant pointer trick below)
    // Codebook pointer is stashed in the first bytes of e2? No — pass as arg instead.
    // (see signature extension below)
    // -- actual load happens in the wrapper version of this kernel --
    // placeholder; real code in vq_main_kernel2
    (void)X; (void)n_points;
}

// Real main kernel (with codebook pointer)
__global__ void __launch_bounds__(TPB, 1)
vq_main(const float* __restrict__ X, const float* __restrict__ E, int n_points) {
    extern __shared__ unsigned char smem_raw[];
    float* buf    = (float*)smem_raw;                 // KC*DC floats
    float* e2     = buf + KC * DC;                    // KC
    int*   sidx   = (int*)(e2 + KC);                  // PPB
    int*   scount = sidx + PPB;                       // KC
    float* red    = (float*)(scount + KC);            // TPB/32 = 16

    const int tid = threadIdx.x;
    const int bid = blockIdx.x;
    const int wid = tid >> 5;
    const int lid = tid & 31;

    if (tid < KC) scount[tid] = 0;

    // ---- load codebook into SMEM (coalesced float4) ----
    {
        const float4* E4 = (const float4*)E;
        float4* B4 = (float4*)buf;
        for (int i = tid; i < KC * D4C; i += TPB) B4[i] = E4[i];
    }
    __syncthreads();

    // ---- per-code squared norms ----
    if (tid < KC) {
        const float4* row = (const float4*)(buf) + tid * D4C;
        float s = 0.0f;
        for (int j = 0; j < D4C; ++j) {
            float4 v = row[j];
            s += v.x * v.x + v.y * v.y + v.z * v.z + v.w * v.w;
        }
        e2[tid] = s;
    }
    __syncthreads();

    // ---- phase 1: distances via packed FFMA2, argmin ----
    const int p = bid * PPB + tid;
    const bool valid = (p < n_points);

    unsigned long long acc[KC];
#pragma unroll
    for (int k = 0; k < KC; ++k) {
        // score_k = x . e_k - 0.5*||e_k||^2 ; argmax score == argmin dist
        acc[k] = (unsigned long long)__float_as_uint(-0.5f * e2[k]);
    }
    unsigned long long sq = 0ull;

    if (valid) {
        const ulonglong2* xr = (const ulonglong2*)(X + (size_t)p * DC);
        const ulonglong2* er = (const ulonglong2*)buf;
        for (int j = 0; j < D4C; ++j) {
            ulonglong2 xv = xr[j];
            sq = fma2(xv.x, xv.x, sq);
            sq = fma2(xv.y, xv.y, sq);
#pragma unroll
            for (int k = 0; k < KC; ++k) {
                ulonglong2 ev = er[k * D4C + j];
                acc[k] = fma2(xv.x, ev.x, acc[k]);
                acc[k] = fma2(xv.y, ev.y, acc[k]);
            }
        }
    }

    int best_i = -1;
    if (valid) {
        float best = -3.4e38f;
        best_i = 0;
#pragma unroll
        for (int k = 0; k < KC; ++k) {
            float s = f2_lo(acc[k]) + f2_hi(acc[k]);
            if (s > best) { best = s; best_i = k; }
        }
        atomicAdd(&scount[best_i], 1);
    }
    sidx[tid] = best_i;

    // ---- sumsq reduction ----
    float mysq = valid ? (f2_lo(sq) + f2_hi(sq)) : 0.0f;
#pragma unroll
    for (int o = 16; o > 0; o >>= 1) mysq += __shfl_xor_sync(0xffffffffu, mysq, o);
    if (lid == 0) red[wid] = mysq;
    __syncthreads();

    // ---- zero dw tile (reuse codebook buffer), thread TPB-1 flushes sumsq ----
    for (int i = tid; i < KC * DC; i += TPB) buf[i] = 0.0f;
    if (tid == TPB - 1) {
        float t = 0.0f;
        for (int w = 0; w < TPB / 32; ++w) t += red[w];
        atomicAdd(&g_sumsq, t);
    }
    __syncthreads();

    // ---- phase 2: segment sum, race-free (thread owns a fixed float4 column) ----
    if (tid < D4C) {
        const float4* X4 = (const float4*)X;
        float4* dw4 = (float4*)buf;
        const size_t base = (size_t)bid * PPB;
        for (int q = 0; q < PPB; ++q) {
            int k = sidx[q];                 // broadcast LDS
            if (k < 0) continue;             // uniform branch (tail block only)
            float4 xv = X4[(base + q) * D4C + tid];
            float4 w = dw4[k * D4C + tid];
            w.x += xv.x; w.y += xv.y; w.z += xv.z; w.w += xv.w;
            dw4[k * D4C + tid] = w;
        }
    }
    __syncthreads();

    // ---- flush block partials to global ----
    for (int i = tid; i < KC * DC; i += TPB) atomicAdd(&g_dw[i], buf[i]);
    if (tid < KC) atomicAdd(&g_counts[tid], (float)scount[tid]);
}

// ---------------- kernel 2: finalize (EMA update + fused loss) --------------
__global__ void vq_finalize(const float* __restrict__ ema_w,
                            const float* __restrict__ ema_cs,
                            float* __restrict__ out, int n_points) {
    __shared__ float csf[KC];
    __shared__ float cnt[KC];
    __shared__ double sred1[8];
    __shared__ double sred2[8];
    const int tid = threadIdx.x;
    const int wid = tid >> 5;
    const int lid = tid & 31;

    if (tid < KC) {
        float c = g_counts[tid];
        cnt[tid] = c;
        csf[tid] = ema_cs[tid] * DECAY + (1.0f - DECAY) * c;
    }
    __syncthreads();
    if (tid == 0) {
        float n = 0.0f;
        for (int k = 0; k < KC; ++k) n += csf[k];
        for (int k = 0; k < KC; ++k)
            csf[k] = (csf[k] + EPSV) / (n + KC * EPSV) * n;
    }
    __syncthreads();

    double s1 = 0.0, s2 = 0.0;
    for (int i = tid; i < KC * DC; i += blockDim.x) {
        int k = i / DC;
        float dwv = g_dw[i];
        float w = ema_w[i] * DECAY + (1.0f - DECAY) * dwv;
        float e = w / csf[k];
        s1 += (double)e * (double)e * (double)cnt[k];
        s2 += (double)e * (double)dwv;
    }
#pragma unroll
    for (int o = 16; o > 0; o >>= 1) {
        s1 += __shfl_xor_sync(0xffffffffu, s1, o);
        s2 += __shfl_xor_sync(0xffffffffu, s2, o);
    }
    if (lid == 0) { sred1[wid] = s1; sred2[wid] = s2; }
    __syncthreads();
    if (tid == 0) {
        double t1 = 0.0, t2 = 0.0;
        int nw = blockDim.x / 32;
        for (int w = 0; w < nw; ++w) { t1 += sred1[w]; t2 += sred2[w]; }
        double loss = (t1 - 2.0 * t2 + (double)g_sumsq) /
                      ((double)n_points * (double)DC);
        out[0] = (float)loss;
    }
}

// ---------------- launcher ---------------------------------------------------
extern "C" void kernel_launch(void* const* d_in, const int* in_sizes, int n_in,
                              void* d_out, int out_size) {
    const float* X      = (const float*)d_in[0];  // [N, D]
    const float* E      = (const float*)d_in[1];  // [K, D]
    const float* ema_w  = (const float*)d_in[2];  // [K, D]
    const float* ema_cs = (const float*)d_in[3];  // [K]
    float* out = (float*)d_out;

    const int n_points = in_sizes[0] / DC;

    const size_t smem = (size_t)(KC * DC) * 4 + KC * 4 + PPB * 4 + KC * 4 + 64;
    static bool attr_set = false;
    if (!attr_set) {
        cudaFuncSetAttribute(vq_main, cudaFuncAttributeMaxDynamicSharedMemorySize,
                             (int)smem);
        attr_set = true;
    }

    vq_zero_kernel<<<(KC * DC + 255) / 256, 256>>>();
    int grid = (n_points + PPB - 1) / PPB;
    vq_main<<<grid, TPB, smem>>>(X, E, n_points);
    vq_finalize<<<1, 256>>>(ema_w, ema_cs, out, n_points);
    (void)n_in; (void)out_size;
}

// round 2
// speedup vs baseline: 1.2052x; 1.2052x over previous
#include <cuda_runtime.h>
#include <cstdint>

// ---------------- problem constants -----------------------------------------
#define KC     40       // codes
#define DC     492      // feature dim
#define D4C    123      // DC / 4
#define D2C    246      // DC / 2
#define TPB    256      // threads per block (main kernel)
#define PASSES 4        // sequential points per thread
#define PPB    (TPB * PASSES)   // 1024 points per block
#define MAXBLK 256      // max main-kernel blocks (N=262144 / 1024)
#define CHUNK  4        // float4 columns staged per chunk
#define XPAD   5        // padded xtile row (float4) to dodge bank conflicts
#define NCHUNK ((D4C + CHUNK - 1) / CHUNK)   // 31

#define DECAY 0.9f
#define EPSV  1e-5f

// ---------------- device-global scratch (no allocations allowed) ------------
__device__ float g_dw_part[MAXBLK][KC * DC];   // per-block dw partials (~20 MB)
__device__ float g_cnt_part[MAXBLK][KC];
__device__ float g_sq_part[MAXBLK];
__device__ float g_dw[KC * DC];
__device__ float g_counts[KC];
__device__ float g_sumsq;

// ---------------- packed f32x2 FMA (Blackwell FFMA2) ------------------------
__device__ __forceinline__ unsigned long long fma2(unsigned long long a,
                                                   unsigned long long b,
                                                   unsigned long long c) {
    unsigned long long d;
    asm("fma.rn.f32x2 %0, %1, %2, %3;" : "=l"(d) : "l"(a), "l"(b), "l"(c));
    return d;
}
__device__ __forceinline__ float f2_lo(unsigned long long v) {
    return __uint_as_float((unsigned)(v & 0xffffffffull));
}
__device__ __forceinline__ float f2_hi(unsigned long long v) {
    return __uint_as_float((unsigned)(v >> 32));
}

// ---------------- dummy kernel (aligns ncu -s 5 onto vq_main) ---------------
__global__ void vq_pad_kernel() {}

// ---------------- kernel 1: assignment + per-block segment sums -------------
// dynamic SMEM layout:
//   float4 xtile[TPB*XPAD]        20480 B   staged X chunk (padded rows)
//   float  cb[KC*DC]              78720 B   codebook (phase1) / dw tile (phase2)
//   float  e2[KC]                   160 B
//   int    sidx[PPB]               4096 B
//   int    scount[KC]               160 B
//   float  red[TPB/32]               32 B
__global__ void __launch_bounds__(TPB, 2)
vq_main(const float* __restrict__ X, const float* __restrict__ E, int n_points) {
    extern __shared__ unsigned char smem_raw[];
    float4* xt4   = (float4*)smem_raw;
    float*  cbf   = (float*)(xt4 + TPB * XPAD);
    float*  e2    = cbf + KC * DC;
    int*    sidx  = (int*)(e2 + KC);
    int*    scount= sidx + PPB;
    float*  red   = (float*)(scount + KC);

    const int tid = threadIdx.x;
    const int bid = blockIdx.x;
    const int wid = tid >> 5;
    const int lid = tid & 31;

    if (tid < KC) scount[tid] = 0;

    // ---- load codebook into SMEM (coalesced float4) ----
    {
        const float4* E4 = (const float4*)E;
        float4* B4 = (float4*)cbf;
        for (int i = tid; i < KC * D4C; i += TPB) B4[i] = E4[i];
    }
    __syncthreads();

    // ---- per-code squared norms ----
    if (tid < KC) {
        const float4* row = (const float4*)cbf + tid * D4C;
        float s = 0.0f;
        for (int j = 0; j < D4C; ++j) {
            float4 v = row[j];
            s += v.x * v.x + v.y * v.y + v.z * v.z + v.w * v.w;
        }
        e2[tid] = s;
    }
    __syncthreads();

    const float4* X4 = (const float4*)X;
    const ulonglong2* cb2 = (const ulonglong2*)cbf;   // codebook as f32x2 pairs
    float sqsum_thread = 0.0f;

    // ---- phase 1: 4 passes of 256 points, chunk-staged, packed FFMA2 -------
    for (int pass = 0; pass < PASSES; ++pass) {
        const int pass_base = bid * PPB + pass * TPB;
        const int p = pass_base + tid;
        const bool valid = (p < n_points);

        unsigned long long acc[KC];
#pragma unroll
        for (int k = 0; k < KC; ++k)
            acc[k] = (unsigned long long)__float_as_uint(-0.5f * e2[k]);
        unsigned long long sq = 0ull;

        for (int c = 0; c < NCHUNK; ++c) {
            const int j0 = c * CHUNK;
            __syncthreads();   // previous chunk fully consumed
            // stage: coalesced-ish (8 rows x 64B per warp)
#pragma unroll
            for (int it = 0; it < CHUNK; ++it) {
                int i   = it * TPB + tid;
                int pt  = i >> 2;
                int off = i & 3;
                int row = pass_base + pt;
                int j   = j0 + off;
                float4 v = make_float4(0.f, 0.f, 0.f, 0.f);
                if (row < n_points && j < D4C)
                    v = X4[(size_t)row * D4C + j];
                xt4[pt * XPAD + off] = v;
            }
            __syncthreads();
            // consume: 4 float4 of own point vs all 40 codes
#pragma unroll
            for (int jj = 0; jj < CHUNK; ++jj) {
                ulonglong2 xv = *(const ulonglong2*)&xt4[tid * XPAD + jj];
                sq = fma2(xv.x, xv.x, sq);
                sq = fma2(xv.y, xv.y, sq);
                const int jidx = j0 + jj;   // may be D4C in tail: x==0 there
#pragma unroll
                for (int k = 0; k < KC; ++k) {
                    ulonglong2 ev = cb2[k * D4C + jidx];
                    acc[k] = fma2(xv.x, ev.x, acc[k]);
                    acc[k] = fma2(xv.y, ev.y, acc[k]);
                }
            }
        }

        int best_i = -1;
        if (valid) {
            float best = -3.4e38f;
            best_i = 0;
#pragma unroll
            for (int k = 0; k < KC; ++k) {
                float s = f2_lo(acc[k]) + f2_hi(acc[k]);
                if (s > best) { best = s; best_i = k; }
            }
            atomicAdd(&scount[best_i], 1);
            sqsum_thread += f2_lo(sq) + f2_hi(sq);
        }
        sidx[pass * TPB + tid] = best_i;
    }

    // ---- block sumsq reduction ----
#pragma unroll
    for (int o = 16; o > 0; o >>= 1)
        sqsum_thread += __shfl_xor_sync(0xffffffffu, sqsum_thread, o);
    if (lid == 0) red[wid] = sqsum_thread;
    __syncthreads();

    // ---- phase 2: zero dw tile (reuse codebook buffer) ----
    for (int i = tid; i < KC * DC; i += TPB) cbf[i] = 0.0f;
    __syncthreads();

    // race-free segment sum: thread owns a fixed float2 column
    if (tid < D2C) {
        const float2* X2 = (const float2*)X;
        const size_t base = (size_t)bid * PPB;
        for (int q = 0; q < PPB; ++q) {
            int k = sidx[q];                 // broadcast LDS
            if (k < 0) continue;
            float2 xv = X2[(base + q) * D2C + tid];
            float2* dst = (float2*)(cbf + k * DC) + tid;
            float2 w = *dst;
            w.x += xv.x; w.y += xv.y;
            *dst = w;
        }
    }
    __syncthreads();

    // ---- flush block partials (plain coalesced stores, no atomics) ----
    for (int i = tid; i < KC * DC; i += TPB) g_dw_part[bid][i] = cbf[i];
    if (tid < KC) g_cnt_part[bid][tid] = (float)scount[tid];
    if (tid == 0) {
        float t = 0.0f;
        for (int w = 0; w < TPB / 32; ++w) t += red[w];
        g_sq_part[bid] = t;
    }
}

// ---------------- kernel 2: reduce per-block partials ------------------------
__global__ void vq_reduce(int nblocks) {
    int e = blockIdx.x * blockDim.x + threadIdx.x;
    if (e < KC * DC) {
        float s = 0.0f;
        for (int b = 0; b < nblocks; ++b) s += g_dw_part[b][e];
        g_dw[e] = s;
    }
    if (e < KC) {
        float s = 0.0f;
        for (int b = 0; b < nblocks; ++b) s += g_cnt_part[b][e];
        g_counts[e] = s;
    }
    if (e == 0) {
        double s = 0.0;
        for (int b = 0; b < nblocks; ++b) s += (double)g_sq_part[b];
        g_sumsq = (float)s;
    }
}

// ---------------- kernel 3: finalize (EMA update + fused loss) --------------
__global__ void vq_finalize(const float* __restrict__ ema_w,
                            const float* __restrict__ ema_cs,
                            float* __restrict__ out, int n_points) {
    __shared__ float csf[KC];
    __shared__ float cnt[KC];
    __shared__ double sred1[8];
    __shared__ double sred2[8];
    const int tid = threadIdx.x;
    const int wid = tid >> 5;
    const int lid = tid & 31;

    if (tid < KC) {
        float c = g_counts[tid];
        cnt[tid] = c;
        csf[tid] = ema_cs[tid] * DECAY + (1.0f - DECAY) * c;
    }
    __syncthreads();
    if (tid == 0) {
        float n = 0.0f;
        for (int k = 0; k < KC; ++k) n += csf[k];
        for (int k = 0; k < KC; ++k)
            csf[k] = (csf[k] + EPSV) / (n + KC * EPSV) * n;
    }
    __syncthreads();

    double s1 = 0.0, s2 = 0.0;
    for (int i = tid; i < KC * DC; i += blockDim.x) {
        int k = i / DC;
        float dwv = g_dw[i];
        float w = ema_w[i] * DECAY + (1.0f - DECAY) * dwv;
        float e = w / csf[k];
        s1 += (double)e * (double)e * (double)cnt[k];
        s2 += (double)e * (double)dwv;
    }
#pragma unroll
    for (int o = 16; o > 0; o >>= 1) {
        s1 += __shfl_xor_sync(0xffffffffu, s1, o);
        s2 += __shfl_xor_sync(0xffffffffu, s2, o);
    }
    if (lid == 0) { sred1[wid] = s1; sred2[wid] = s2; }
    __syncthreads();
    if (tid == 0) {
        double t1 = 0.0, t2 = 0.0;
        int nw = blockDim.x / 32;
        for (int w = 0; w < nw; ++w) { t1 += sred1[w]; t2 += sred2[w]; }
        double loss = (t1 - 2.0 * t2 + (double)g_sumsq) /
                      ((double)n_points * (double)DC);
        out[0] = (float)loss;
    }
}

// ---------------- launcher ---------------------------------------------------
extern "C" void kernel_launch(void* const* d_in, const int* in_sizes, int n_in,
                              void* d_out, int out_size) {
    const float* X      = (const float*)d_in[0];  // [N, D]
    const float* E      = (const float*)d_in[1];  // [K, D]
    const float* ema_w  = (const float*)d_in[2];  // [K, D]
    const float* ema_cs = (const float*)d_in[3];  // [K]
    float* out = (float*)d_out;

    const int n_points = in_sizes[0] / DC;
    int grid = (n_points + PPB - 1) / PPB;
    if (grid > MAXBLK) grid = MAXBLK;   // dataset: exactly 256

    const size_t smem = (size_t)(TPB * XPAD) * 16      // xtile
                      + (size_t)(KC * DC) * 4          // codebook / dw tile
                      + KC * 4                          // e2
                      + PPB * 4                         // sidx
                      + KC * 4                          // scount
                      + (TPB / 32) * 4;                 // red
    cudaFuncSetAttribute(vq_main, cudaFuncAttributeMaxDynamicSharedMemorySize,
                         (int)smem);

    vq_pad_kernel<<<1, 32>>>();                         // ncu -s 5 alignment
    vq_main<<<grid, TPB, smem>>>(X, E, n_points);
    vq_reduce<<<(KC * DC + 255) / 256, 256>>>(grid);
    vq_finalize<<<1, 256>>>(ema_w, ema_cs, out, n_points);
    (void)n_in; (void)out_size;
}

// round 3
// speedup vs baseline: 1.3634x; 1.1312x over previous
#include <cuda_runtime.h>
#include <cstdint>

// ---------------- problem constants -----------------------------------------
#define KC     40      // codes
#define KP     20      // code pairs (f32x2 packing along K)
#define DC     492     // feature dim
#define D4C    123     // DC / 4
#define TPB    128     // threads per block (main kernel)
#define CPT    4       // concurrent points per thread
#define GRPS   2       // sequential groups per block
#define GP     (TPB * CPT)        // 512 points per group
#define PPB    (GP * GRPS)        // 1024 points per block
#define MAXBLK 256
#define F4PC   3       // float4 per point per chunk
#define DCHUNK 12      // floats per point per chunk
#define NCHUNK 41      // 492 / 12

#define DECAY 0.9f
#define EPSV  1e-5f

typedef unsigned long long u64;

// ---------------- device-global scratch -------------------------------------
__device__ float g_dw_part[MAXBLK][KC * DC];   // ~20 MB
__device__ float g_cnt_part[MAXBLK][KC];
__device__ float g_sq_part[MAXBLK];
__device__ float g_dw[KC * DC];
__device__ float g_counts[KC];
__device__ float g_sumsq;

// ---------------- packed f32x2 helpers (Blackwell FFMA2) --------------------
__device__ __forceinline__ u64 fma2(u64 a, u64 b, u64 c) {
    u64 d;
    asm("fma.rn.f32x2 %0, %1, %2, %3;" : "=l"(d) : "l"(a), "l"(b), "l"(c));
    return d;
}
__device__ __forceinline__ float f2_lo(u64 v) {
    return __uint_as_float((unsigned)(v & 0xffffffffull));
}
__device__ __forceinline__ float f2_hi(u64 v) {
    return __uint_as_float((unsigned)(v >> 32));
}
__device__ __forceinline__ u64 rep_lo(u64 v) {
    unsigned r = (unsigned)v; u64 o;
    asm("mov.b64 %0, {%1, %1};" : "=l"(o) : "r"(r));
    return o;
}
__device__ __forceinline__ u64 rep_hi(u64 v) {
    unsigned r = (unsigned)(v >> 32); u64 o;
    asm("mov.b64 %0, {%1, %1};" : "=l"(o) : "r"(r));
    return o;
}

// ---------------- pad kernels (put vq_main at absolute launch idx 3) --------
__global__ void vq_pad() {}

// ---------------- kernel: assignment + per-block segment sums ---------------
// dynamic SMEM:
//   u64   xtu[6*GP]      24576 B  transposed x tile: [d-pair][point]
//   float cbT[DC*KC]     78720 B  transposed codebook (phase1) / dw tile (ph2)
//   u64   e2p[KP]          160 B  packed -0.5*||e||^2 pairs
//   int   sidx[PPB]       4096 B
//   int   scount[KC]       160 B
//   float red[4]            16 B
__global__ void __launch_bounds__(TPB, 2)
vq_main(const float* __restrict__ X, const float* __restrict__ E, int n_points) {
    extern __shared__ unsigned char sraw[];
    u64*   xtu    = (u64*)sraw;
    float* cbT    = (float*)(xtu + 6 * GP);
    u64*   e2p    = (u64*)(cbT + DC * KC);
    int*   sidx   = (int*)(e2p + KP);
    int*   scount = sidx + PPB;
    float* red    = (float*)(scount + KC);
    float* e2tmp  = (float*)sidx;          // transient reuse before sidx written

    const int t   = threadIdx.x;
    const int bid = blockIdx.x;
    const int wid = t >> 5;
    const int lid = t & 31;

    if (t < KC) scount[t] = 0;

    // ---- load + transpose codebook into SMEM: cbT[d][k] ----
    {
        const float4* E4 = (const float4*)E;
        for (int i = t; i < KC * D4C; i += TPB) {
            int k = i / D4C;
            int j = i - k * D4C;
            float4 v = E4[i];
            cbT[(4 * j + 0) * KC + k] = v.x;
            cbT[(4 * j + 1) * KC + k] = v.y;
            cbT[(4 * j + 2) * KC + k] = v.z;
            cbT[(4 * j + 3) * KC + k] = v.w;
        }
    }
    __syncthreads();

    // ---- per-code squared norms -> packed -0.5*e2 pairs ----
    if (t < KC) {
        float s = 0.0f;
        for (int d = 0; d < DC; ++d) {
            float v = cbT[d * KC + t];
            s += v * v;
        }
        e2tmp[t] = s;
    }
    __syncthreads();
    if (t < KP) {
        unsigned ua = __float_as_uint(-0.5f * e2tmp[2 * t]);
        unsigned ub = __float_as_uint(-0.5f * e2tmp[2 * t + 1]);
        e2p[t] = ((u64)ub << 32) | (u64)ua;
    }
    __syncthreads();

    const ulonglong2* Xu = (const ulonglong2*)X;   // float4 granularity
    float sq_total = 0.0f;

    // ================= phase 1: scores + argmin =============================
    for (int grp = 0; grp < GRPS; ++grp) {
        const int gbase = bid * PPB + grp * GP;

        u64 acc[CPT][KP];
#pragma unroll
        for (int kp = 0; kp < KP; ++kp) {
            u64 e = e2p[kp];
#pragma unroll
            for (int g = 0; g < CPT; ++g) acc[g][kp] = e;
        }
        u64 sq[CPT];
#pragma unroll
        for (int g = 0; g < CPT; ++g) sq[g] = 0ull;

        for (int c = 0; c < NCHUNK; ++c) {
            __syncthreads();    // previous chunk consumed
            // ---- stage 512 points x 12 floats, transposed ----
#pragma unroll
            for (int it = 0; it < 12; ++it) {
                int i  = it * TPB + t;      // 0..1535
                int pt = i / 3;
                int jh = i - 3 * pt;
                int row = gbase + pt;
                ulonglong2 v;
                v.x = 0ull; v.y = 0ull;
                if (row < n_points)
                    v = Xu[(size_t)row * D4C + c * F4PC + jh];
                xtu[(2 * jh) * GP + pt]     = v.x;   // (d, d+1) pair
                xtu[(2 * jh + 1) * GP + pt] = v.y;   // (d+2, d+3) pair
            }
            __syncthreads();

            // ---- consume: 6 d-pairs ----
#pragma unroll
            for (int dp = 0; dp < 6; ++dp) {
                u64 xp[CPT];
#pragma unroll
                for (int g = 0; g < CPT; ++g) {
                    xp[g] = xtu[dp * GP + g * TPB + t];
                    sq[g] = fma2(xp[g], xp[g], sq[g]);
                }
#pragma unroll
                for (int half = 0; half < 2; ++half) {
                    const ulonglong2* crow =
                        (const ulonglong2*)(cbT + (c * DCHUNK + 2 * dp + half) * KC);
                    u64 xr[CPT];
#pragma unroll
                    for (int g = 0; g < CPT; ++g)
                        xr[g] = half ? rep_hi(xp[g]) : rep_lo(xp[g]);
#pragma unroll
                    for (int k2 = 0; k2 < 10; ++k2) {
                        ulonglong2 ev = crow[k2];   // codes 4k2..4k2+3 at dim d
#pragma unroll
                        for (int g = 0; g < CPT; ++g) {
                            acc[g][2 * k2]     = fma2(xr[g], ev.x, acc[g][2 * k2]);
                            acc[g][2 * k2 + 1] = fma2(xr[g], ev.y, acc[g][2 * k2 + 1]);
                        }
                    }
                }
            }
        }

        // ---- argmin (max score) per point ----
#pragma unroll
        for (int g = 0; g < CPT; ++g) {
            int p = gbase + g * TPB + t;
            int bi = -1;
            if (p < n_points) {
                float best = -3.4e38f;
                bi = 0;
#pragma unroll
                for (int kp = 0; kp < KP; ++kp) {
                    float slo = f2_lo(acc[g][kp]);
                    float shi = f2_hi(acc[g][kp]);
                    if (slo > best) { best = slo; bi = 2 * kp; }
                    if (shi > best) { best = shi; bi = 2 * kp + 1; }
                }
                atomicAdd(&scount[bi], 1);
                sq_total += f2_lo(sq[g]) + f2_hi(sq[g]);
            }
            sidx[grp * GP + g * TPB + t] = bi;
        }
    }

    // ---- block sumsq reduction ----
#pragma unroll
    for (int o = 16; o > 0; o >>= 1)
        sq_total += __shfl_xor_sync(0xffffffffu, sq_total, o);
    if (lid == 0) red[wid] = sq_total;
    __syncthreads();

    // ================= phase 2: segment sum (race-free columns) =============
    for (int i = t; i < KC * DC; i += TPB) cbT[i] = 0.0f;
    __syncthreads();

    if (t < D4C) {
        const float4* X4 = (const float4*)X;
        float4* dw4 = (float4*)cbT;
        const size_t base = (size_t)bid * PPB;
        for (int q = 0; q < PPB; ++q) {
            int k = sidx[q];                 // broadcast LDS
            if (k < 0) continue;
            float4 xv = X4[(base + q) * D4C + t];
            float4* dst = dw4 + k * D4C + t;
            float4 w = *dst;
            w.x += xv.x; w.y += xv.y; w.z += xv.z; w.w += xv.w;
            *dst = w;
        }
    }
    __syncthreads();

    // ---- flush block partials (coalesced stores, no atomics) ----
    for (int i = t; i < KC * DC; i += TPB) g_dw_part[bid][i] = cbT[i];
    if (t < KC) g_cnt_part[bid][t] = (float)scount[t];
    if (t == 0) {
        float s = red[0] + red[1] + red[2] + red[3];
        g_sq_part[bid] = s;
    }
}

// ---------------- kernel: reduce per-block partials --------------------------
__global__ void vq_reduce(int nblocks) {
    int e = blockIdx.x * blockDim.x + threadIdx.x;
    if (e < KC * DC) {
        float s0 = 0.f, s1 = 0.f, s2 = 0.f, s3 = 0.f;
        int b = 0;
        for (; b + 4 <= nblocks; b += 4) {
            s0 += g_dw_part[b + 0][e];
            s1 += g_dw_part[b + 1][e];
            s2 += g_dw_part[b + 2][e];
            s3 += g_dw_part[b + 3][e];
        }
        float s = (s0 + s1) + (s2 + s3);
        for (; b < nblocks; ++b) s += g_dw_part[b][e];
        g_dw[e] = s;
    }
    if (e < KC) {
        float s = 0.f;
        for (int b = 0; b < nblocks; ++b) s += g_cnt_part[b][e];
        g_counts[e] = s;
    }
    if (e == 0) {
        double s = 0.0;
        for (int b = 0; b < nblocks; ++b) s += (double)g_sq_part[b];
        g_sumsq = (float)s;
    }
}

// ---------------- kernel: finalize (EMA update + fused loss) ----------------
__global__ void vq_finalize(const float* __restrict__ ema_w,
                            const float* __restrict__ ema_cs,
                            float* __restrict__ out, int n_points) {
    __shared__ float csf[KC];
    __shared__ float cnt[KC];
    __shared__ double sred1[32];
    __shared__ double sred2[32];
    const int tid = threadIdx.x;
    const int wid = tid >> 5;
    const int lid = tid & 31;

    if (tid < KC) {
        float c = g_counts[tid];
        cnt[tid] = c;
        csf[tid] = ema_cs[tid] * DECAY + (1.0f - DECAY) * c;
    }
    __syncthreads();
    if (tid == 0) {
        float n = 0.0f;
        for (int k = 0; k < KC; ++k) n += csf[k];
        for (int k = 0; k < KC; ++k)
            csf[k] = (csf[k] + EPSV) / (n + KC * EPSV) * n;
    }
    __syncthreads();

    double s1 = 0.0, s2 = 0.0;
#pragma unroll 4
    for (int i = tid; i < KC * DC; i += blockDim.x) {
        int k = i / DC;
        float dwv = g_dw[i];
        float w = ema_w[i] * DECAY + (1.0f - DECAY) * dwv;
        float e = w / csf[k];
        s1 += (double)e * (double)e * (double)cnt[k];
        s2 += (double)e * (double)dwv;
    }
#pragma unroll
    for (int o = 16; o > 0; o >>= 1) {
        s1 += __shfl_xor_sync(0xffffffffu, s1, o);
        s2 += __shfl_xor_sync(0xffffffffu, s2, o);
    }
    if (lid == 0) { sred1[wid] = s1; sred2[wid] = s2; }
    __syncthreads();
    if (tid == 0) {
        double t1 = 0.0, t2 = 0.0;
        int nw = blockDim.x / 32;
        for (int w = 0; w < nw; ++w) { t1 += sred1[w]; t2 += sred2[w]; }
        double loss = (t1 - 2.0 * t2 + (double)g_sumsq) /
                      ((double)n_points * (double)DC);
        out[0] = (float)loss;
    }
}

// ---------------- launcher ---------------------------------------------------
extern "C" void kernel_launch(void* const* d_in, const int* in_sizes, int n_in,
                              void* d_out, int out_size) {
    const float* X      = (const float*)d_in[0];
    const float* E      = (const float*)d_in[1];
    const float* ema_w  = (const float*)d_in[2];
    const float* ema_cs = (const float*)d_in[3];
    float* out = (float*)d_out;

    const int n_points = in_sizes[0] / DC;
    int grid = (n_points + PPB - 1) / PPB;
    if (grid > MAXBLK) grid = MAXBLK;   // dataset: exactly 256

    const size_t smem = (size_t)(6 * GP) * 8        // xtu
                      + (size_t)(DC * KC) * 4       // cbT
                      + KP * 8                       // e2p
                      + PPB * 4                      // sidx
                      + KC * 4                       // scount
                      + 4 * 4;                       // red
    cudaFuncSetAttribute(vq_main, cudaFuncAttributeMaxDynamicSharedMemorySize,
                         (int)smem);

    vq_pad<<<1, 32>>>();                // idx 0
    vq_pad<<<1, 32>>>();                // idx 1
    vq_pad<<<1, 32>>>();                // idx 2
    vq_main<<<grid, TPB, smem>>>(X, E, n_points);        // idx 3 <- ncu target
    vq_reduce<<<(KC * DC + 255) / 256, 256>>>(grid);
    vq_finalize<<<1, 1024>>>(ema_w, ema_cs, out, n_points);
    (void)n_in; (void)out_size;
}

// round 4
// speedup vs baseline: 1.3864x; 1.0168x over previous
#include <cuda_runtime.h>
#include <cstdint>

// ---------------- problem constants -----------------------------------------
#define KC     40      // codes
#define KP     20      // code pairs (f32x2 packing along K)
#define DC     492     // feature dim
#define D4C    123     // DC / 4
#define D2C    246     // DC / 2
#define TPB    256     // threads per block (main kernel)
#define CPT    2       // concurrent points per thread
#define GRPS   2       // sequential groups per block
#define GP     (TPB * CPT)        // 512 points per group
#define PPB    (GP * GRPS)        // 1024 points per block
#define MAXBLK 256
#define F4PC   3       // float4 per point per chunk
#define DCHUNK 12      // floats per point per chunk
#define NCHUNK 41      // 492 / 12

#define DECAY 0.9f
#define EPSV  1e-5f

typedef unsigned long long u64;

// ---------------- device-global scratch -------------------------------------
__device__ float g_dw_part[MAXBLK][KC * DC];   // ~20 MB
__device__ float g_cnt_part[MAXBLK][KC];
__device__ float g_sq_part[MAXBLK];
__device__ float g_dw[KC * DC];
__device__ float g_counts[KC];
__device__ float g_sumsq;

// ---------------- packed f32x2 helpers (Blackwell FFMA2) --------------------
__device__ __forceinline__ u64 fma2(u64 a, u64 b, u64 c) {
    u64 d;
    asm("fma.rn.f32x2 %0, %1, %2, %3;" : "=l"(d) : "l"(a), "l"(b), "l"(c));
    return d;
}
__device__ __forceinline__ float f2_lo(u64 v) {
    return __uint_as_float((unsigned)(v & 0xffffffffull));
}
__device__ __forceinline__ float f2_hi(u64 v) {
    return __uint_as_float((unsigned)(v >> 32));
}
__device__ __forceinline__ u64 rep_lo(u64 v) {
    unsigned r = (unsigned)v; u64 o;
    asm("mov.b64 %0, {%1, %1};" : "=l"(o) : "r"(r));
    return o;
}
__device__ __forceinline__ u64 rep_hi(u64 v) {
    unsigned r = (unsigned)(v >> 32); u64 o;
    asm("mov.b64 %0, {%1, %1};" : "=l"(o) : "r"(r));
    return o;
}

// ---------------- pad kernels (put vq_main at absolute launch idx 3) --------
__global__ void vq_pad() {}

// ---------------- kernel: assignment + per-block segment sums ---------------
// dynamic SMEM (107,744 B total; 2 CTAs/SM):
//   u64   xtu[6*GP]      24576 B  transposed x tile: [d-pair][point]
//   float cbT[DC*KC]     78720 B  transposed codebook (phase1) / dw tile (ph2)
//   u64   e2p[KP]          160 B  packed -0.5*||e||^2 pairs
//   int   sidx[PPB]       4096 B
//   int   scount[KC]       160 B
//   float red[8]            32 B
__global__ void __launch_bounds__(TPB, 2)
vq_main(const float* __restrict__ X, const float* __restrict__ E, int n_points) {
    extern __shared__ unsigned char sraw[];
    u64*   xtu    = (u64*)sraw;
    float* cbT    = (float*)(xtu + 6 * GP);
    u64*   e2p    = (u64*)(cbT + DC * KC);
    int*   sidx   = (int*)(e2p + KP);
    int*   scount = sidx + PPB;
    float* red    = (float*)(scount + KC);
    float* e2tmp  = (float*)sidx;          // transient reuse before sidx written

    const int t   = threadIdx.x;
    const int bid = blockIdx.x;
    const int wid = t >> 5;
    const int lid = t & 31;

    if (t < KC) scount[t] = 0;

    // ---- load + transpose codebook into SMEM: cbT[d][k] ----
    {
        const float4* E4 = (const float4*)E;
        for (int i = t; i < KC * D4C; i += TPB) {
            int k = i / D4C;
            int j = i - k * D4C;
            float4 v = E4[i];
            cbT[(4 * j + 0) * KC + k] = v.x;
            cbT[(4 * j + 1) * KC + k] = v.y;
            cbT[(4 * j + 2) * KC + k] = v.z;
            cbT[(4 * j + 3) * KC + k] = v.w;
        }
    }
    __syncthreads();

    // ---- per-code squared norms -> packed -0.5*e2 pairs ----
    if (t < KC) {
        float s = 0.0f;
        for (int d = 0; d < DC; ++d) {
            float v = cbT[d * KC + t];
            s += v * v;
        }
        e2tmp[t] = s;
    }
    __syncthreads();
    if (t < KP) {
        unsigned ua = __float_as_uint(-0.5f * e2tmp[2 * t]);
        unsigned ub = __float_as_uint(-0.5f * e2tmp[2 * t + 1]);
        e2p[t] = ((u64)ub << 32) | (u64)ua;
    }
    __syncthreads();

    const ulonglong2* Xu = (const ulonglong2*)X;   // float4 granularity
    float sq_total = 0.0f;

    // ================= phase 1: scores + argmin =============================
    for (int grp = 0; grp < GRPS; ++grp) {
        const int gbase = bid * PPB + grp * GP;

        u64 acc[CPT][KP];
#pragma unroll
        for (int kp = 0; kp < KP; ++kp) {
            u64 e = e2p[kp];
#pragma unroll
            for (int g = 0; g < CPT; ++g) acc[g][kp] = e;
        }
        u64 sq[CPT];
#pragma unroll
        for (int g = 0; g < CPT; ++g) sq[g] = 0ull;

        for (int c = 0; c < NCHUNK; ++c) {
            __syncthreads();    // previous chunk consumed
            // ---- stage 512 points x 12 floats, transposed ----
#pragma unroll
            for (int it = 0; it < 6; ++it) {
                int i  = it * TPB + t;      // 0..1535
                int pt = i / 3;
                int jh = i - 3 * pt;
                int row = gbase + pt;
                ulonglong2 v;
                v.x = 0ull; v.y = 0ull;
                if (row < n_points)
                    v = Xu[(size_t)row * D4C + c * F4PC + jh];
                xtu[(2 * jh) * GP + pt]     = v.x;   // (d, d+1) pair
                xtu[(2 * jh + 1) * GP + pt] = v.y;   // (d+2, d+3) pair
            }
            __syncthreads();

            // ---- consume: 6 d-pairs ----
#pragma unroll
            for (int dp = 0; dp < 6; ++dp) {
                u64 xp[CPT];
#pragma unroll
                for (int g = 0; g < CPT; ++g) {
                    xp[g] = xtu[dp * GP + g * TPB + t];
                    sq[g] = fma2(xp[g], xp[g], sq[g]);
                }
#pragma unroll
                for (int half = 0; half < 2; ++half) {
                    const ulonglong2* crow =
                        (const ulonglong2*)(cbT + (c * DCHUNK + 2 * dp + half) * KC);
                    u64 xr[CPT];
#pragma unroll
                    for (int g = 0; g < CPT; ++g)
                        xr[g] = half ? rep_hi(xp[g]) : rep_lo(xp[g]);
#pragma unroll
                    for (int k2 = 0; k2 < 10; ++k2) {
                        ulonglong2 ev = crow[k2];   // codes 4k2..4k2+3 at dim d
#pragma unroll
                        for (int g = 0; g < CPT; ++g) {
                            acc[g][2 * k2]     = fma2(xr[g], ev.x, acc[g][2 * k2]);
                            acc[g][2 * k2 + 1] = fma2(xr[g], ev.y, acc[g][2 * k2 + 1]);
                        }
                    }
                }
            }
        }

        // ---- argmin (max score) per point ----
#pragma unroll
        for (int g = 0; g < CPT; ++g) {
            int p = gbase + g * TPB + t;
            int bi = -1;
            if (p < n_points) {
                float best = -3.4e38f;
                bi = 0;
#pragma unroll
                for (int kp = 0; kp < KP; ++kp) {
                    float slo = f2_lo(acc[g][kp]);
                    float shi = f2_hi(acc[g][kp]);
                    if (slo > best) { best = slo; bi = 2 * kp; }
                    if (shi > best) { best = shi; bi = 2 * kp + 1; }
                }
                atomicAdd(&scount[bi], 1);
                sq_total += f2_lo(sq[g]) + f2_hi(sq[g]);
            }
            sidx[grp * GP + g * TPB + t] = bi;
        }
    }

    // ---- block sumsq reduction ----
#pragma unroll
    for (int o = 16; o > 0; o >>= 1)
        sq_total += __shfl_xor_sync(0xffffffffu, sq_total, o);
    if (lid == 0) red[wid] = sq_total;
    __syncthreads();

    // ================= phase 2: segment sum (race-free float2 columns) ======
    for (int i = t; i < KC * DC; i += TPB) cbT[i] = 0.0f;
    __syncthreads();

    if (t < D2C) {
        const float2* X2 = (const float2*)X;
        float2* dw2 = (float2*)cbT;
        const size_t base = (size_t)bid * PPB;
        for (int q = 0; q < PPB; ++q) {
            int k = sidx[q];                 // broadcast LDS
            if (k < 0) continue;
            float2 xv = X2[(base + q) * D2C + t];
            float2* dst = dw2 + k * D2C + t;
            float2 w = *dst;
            w.x += xv.x; w.y += xv.y;
            *dst = w;
        }
    }
    __syncthreads();

    // ---- flush block partials (coalesced stores, no atomics) ----
    for (int i = t; i < KC * DC; i += TPB) g_dw_part[bid][i] = cbT[i];
    if (t < KC) g_cnt_part[bid][t] = (float)scount[t];
    if (t == 0) {
        float s = 0.0f;
        for (int w = 0; w < TPB / 32; ++w) s += red[w];
        g_sq_part[bid] = s;
    }
}

// ---------------- kernel: reduce per-block partials --------------------------
__global__ void vq_reduce(int nblocks) {
    int e = blockIdx.x * blockDim.x + threadIdx.x;
    if (e < KC * DC) {
        float s0 = 0.f, s1 = 0.f, s2 = 0.f, s3 = 0.f;
        int b = 0;
        for (; b + 4 <= nblocks; b += 4) {
            s0 += g_dw_part[b + 0][e];
            s1 += g_dw_part[b + 1][e];
            s2 += g_dw_part[b + 2][e];
            s3 += g_dw_part[b + 3][e];
        }
        float s = (s0 + s1) + (s2 + s3);
        for (; b < nblocks; ++b) s += g_dw_part[b][e];
        g_dw[e] = s;
    }
    if (e < KC) {
        float s = 0.f;
        for (int b = 0; b < nblocks; ++b) s += g_cnt_part[b][e];
        g_counts[e] = s;
    }
    if (e == 0) {
        double s = 0.0;
        for (int b = 0; b < nblocks; ++b) s += (double)g_sq_part[b];
        g_sumsq = (float)s;
    }
}

// ---------------- kernel: finalize (EMA update + fused loss) ----------------
__global__ void vq_finalize(const float* __restrict__ ema_w,
                            const float* __restrict__ ema_cs,
                            float* __restrict__ out, int n_points) {
    __shared__ float csf[KC];
    __shared__ float cnt[KC];
    __shared__ double sred1[32];
    __shared__ double sred2[32];
    const int tid = threadIdx.x;
    const int wid = tid >> 5;
    const int lid = tid & 31;

    if (tid < KC) {
        float c = g_counts[tid];
        cnt[tid] = c;
        csf[tid] = ema_cs[tid] * DECAY + (1.0f - DECAY) * c;
    }
    __syncthreads();
    if (tid == 0) {
        float n = 0.0f;
        for (int k = 0; k < KC; ++k) n += csf[k];
        for (int k = 0; k < KC; ++k)
            csf[k] = (csf[k] + EPSV) / (n + KC * EPSV) * n;
    }
    __syncthreads();

    double s1 = 0.0, s2 = 0.0;
#pragma unroll 4
    for (int i = tid; i < KC * DC; i += blockDim.x) {
        int k = i / DC;
        float dwv = g_dw[i];
        float w = ema_w[i] * DECAY + (1.0f - DECAY) * dwv;
        float e = w / csf[k];
        s1 += (double)e * (double)e * (double)cnt[k];
        s2 += (double)e * (double)dwv;
    }
#pragma unroll
    for (int o = 16; o > 0; o >>= 1) {
        s1 += __shfl_xor_sync(0xffffffffu, s1, o);
        s2 += __shfl_xor_sync(0xffffffffu, s2, o);
    }
    if (lid == 0) { sred1[wid] = s1; sred2[wid] = s2; }
    __syncthreads();
    if (tid == 0) {
        double t1 = 0.0, t2 = 0.0;
        int nw = blockDim.x / 32;
        for (int w = 0; w < nw; ++w) { t1 += sred1[w]; t2 += sred2[w]; }
        double loss = (t1 - 2.0 * t2 + (double)g_sumsq) /
                      ((double)n_points * (double)DC);
        out[0] = (float)loss;
    }
}

// ---------------- launcher ---------------------------------------------------
extern "C" void kernel_launch(void* const* d_in, const int* in_sizes, int n_in,
                              void* d_out, int out_size) {
    const float* X      = (const float*)d_in[0];
    const float* E      = (const float*)d_in[1];
    const float* ema_w  = (const float*)d_in[2];
    const float* ema_cs = (const float*)d_in[3];
    float* out = (float*)d_out;

    const int n_points = in_sizes[0] / DC;
    int grid = (n_points + PPB - 1) / PPB;
    if (grid > MAXBLK) grid = MAXBLK;   // dataset: exactly 256

    const size_t smem = (size_t)(6 * GP) * 8        // xtu
                      + (size_t)(DC * KC) * 4       // cbT
                      + KP * 8                       // e2p
                      + PPB * 4                      // sidx
                      + KC * 4                       // scount
                      + (TPB / 32) * 4;              // red
    cudaFuncSetAttribute(vq_main, cudaFuncAttributeMaxDynamicSharedMemorySize,
                         (int)smem);

    vq_pad<<<1, 32>>>();                // idx 0
    vq_pad<<<1, 32>>>();                // idx 1
    vq_pad<<<1, 32>>>();                // idx 2
    vq_main<<<grid, TPB, smem>>>(X, E, n_points);        // idx 3 <- ncu target
    vq_reduce<<<(KC * DC + 255) / 256, 256>>>(grid);
    vq_finalize<<<1, 1024>>>(ema_w, ema_cs, out, n_points);
    (void)n_in; (void)out_size;
}